// round 17
// baseline (speedup 1.0000x reference)
#include <cuda_runtime.h>
#include <cstdint>

#define DIMN 384
#define NP 192                    // logical uint2 slots per B row (full K)
#define PSB 52                    // B pitch in uint2 (48 data + 4 pad)
#define A4_CNT 3072               // uint4 per 32-row A block (full K)
#define A4_PER_CHUNK 768          // uint4 per K=96 chunk
#define ABYTES_C (A4_PER_CHUNK * 16)      // 12288
#define BPAD_CHUNK (32 * PSB)
#define BBYTES_C (BPAD_CHUNK * 8) // 13312
#define STAGE_B (ABYTES_C + BBYTES_C)     // 25600
#define SMEM_GEMM (2 * STAGE_B)   // 51200 -> 4 CTAs/SM
#define FP4PITCH 97               // staged row pitch in float4
#define SMEM_PACK (16 * FP4PITCH * 16)    // 24832 (16-row staging)

// Scratch (no cudaMalloc allowed)
__device__ __align__(16) uint4 g_v1p4[32 * A4_CNT];
__device__ __align__(16) uint4 g_tp4[32 * A4_CNT];
__device__ __align__(16) uint2 g_lwp[12 * 4 * BPAD_CHUNK];
__device__ __align__(16) uint2 g_Ptp[12 * 4 * BPAD_CHUNK];
__device__ float g_cbarp[24][DIMN];       // racefree per-(bi,half) cbar partials

__device__ __forceinline__ uint32_t f2tf32(float x) {
    uint32_t y; asm("cvt.rna.tf32.f32 %0, %1;" : "=r"(y) : "f"(x)); return y;
}
__device__ __forceinline__ uint32_t smem_u32(const void* p) {
    uint32_t a;
    asm("{ .reg .u64 t; cvta.to.shared.u64 t, %1; cvt.u32.u64 %0, t; }" : "=r"(a) : "l"(p));
    return a;
}
__device__ __forceinline__ void mbar_init(uint32_t mb, uint32_t cnt) {
    asm volatile("mbarrier.init.shared.b64 [%0], %1;" :: "r"(mb), "r"(cnt) : "memory");
}
__device__ __forceinline__ void mbar_expect(uint32_t mb, uint32_t tx) {
    asm volatile("mbarrier.arrive.expect_tx.shared.b64 _, [%0], %1;" :: "r"(mb), "r"(tx) : "memory");
}
#define MBAR_WAIT(mb, ph) do { \
    asm volatile("{\n\t.reg .pred P1;\n\t" \
        "WAIT_LOOP_%=:\n\t" \
        "mbarrier.try_wait.parity.acquire.cta.shared::cta.b64 P1, [%0], %1, 0x989680;\n\t" \
        "@P1 bra.uni WAIT_DONE_%=;\n\t" \
        "bra.uni WAIT_LOOP_%=;\n\t" \
        "WAIT_DONE_%=:\n\t}" :: "r"(mb), "r"((uint32_t)(ph)) : "memory"); \
} while (0)
__device__ __forceinline__ void bulk_g2s(uint32_t dst, const void* src,
                                         uint32_t bytes, uint32_t mb) {
    asm volatile(
        "cp.async.bulk.shared::cluster.global.mbarrier::complete_tx::bytes [%0], [%1], %2, [%3];"
        :: "r"(dst), "l"(src), "r"(bytes), "r"(mb) : "memory");
}
__device__ __forceinline__ void mma8(float* d, const uint32_t* a, uint32_t b0, uint32_t b1) {
    asm("mma.sync.aligned.m16n8k8.row.col.f32.tf32.tf32.f32 "
        "{%0,%1,%2,%3}, {%4,%5,%6,%7}, {%8,%9}, {%0,%1,%2,%3};"
        : "+f"(d[0]), "+f"(d[1]), "+f"(d[2]), "+f"(d[3])
        : "r"(a[0]), "r"(a[1]), "r"(a[2]), "r"(a[3]), "r"(b0), "r"(b1));
}

// ---------------------------------------------------------------------------
// pack_prep: 376 CTAs, three roles, all coalesced + high-MLP.
//   bid <  288: prep half-tile (bi, bih, bj): 16 rows x 32 cols
//   288..351  : v1 pack (rb, row-half)
//   352..375  : linW pack (nb, row-half)
// ---------------------------------------------------------------------------
__global__ __launch_bounds__(256)
void pack_prep_kernel(const float* __restrict__ v1, const float* __restrict__ linW,
                      const float* __restrict__ W, const float* __restrict__ Bb,
                      const float* __restrict__ rw, int nblocks) {
    extern __shared__ __align__(16) char smc[];
    const int bid = blockIdx.x, tid = threadIdx.x;

    if (bid < 288) {
        // ---- prep half-tile: 16 rows x 32 cols, float2/thread ----
        float* pt = (float*)smc;           // 16 x 33
        float* cp = pt + 16 * 33;
        const int bi2 = bid % 24, bj = bid / 24;
        const int bi = bi2 >> 1, bih = bi2 & 1;
        const int row = tid >> 4;              // 0..15
        const int cl = (tid & 15) * 2;         // 0..30
        const int gi = bi * 32 + bih * 16 + row;
        const int gj = bj * 32 + cl;
        const size_t off = (size_t)gi * DIMN + gj;
        const size_t stride = (size_t)DIMN * DIMN;

        float2 p, c;
        if (nblocks == 3) {
            float2 w0 = *(const float2*)&W[off];
            float2 w1 = *(const float2*)&W[off + stride];
            float2 w2 = *(const float2*)&W[off + 2 * stride];
            float2 b0 = *(const float2*)&Bb[off];
            float2 b1 = *(const float2*)&Bb[off + stride];
            float2 b2 = *(const float2*)&Bb[off + 2 * stride];
            float2 o0 = make_float2(1.f - w0.x, 1.f - w0.y);
            float2 o1 = make_float2(1.f - w1.x, 1.f - w1.y);
            float2 o2 = make_float2(1.f - w2.x, 1.f - w2.y);
            p = make_float2(o0.x * o1.x * o2.x, o0.y * o1.y * o2.y);
            c = make_float2((b0.x * o1.x + b1.x) * o2.x + b2.x,
                            (b0.y * o1.y + b1.y) * o2.y + b2.y);
        } else {
            p = make_float2(1.f, 1.f);
            c = make_float2(0.f, 0.f);
            for (int k = 0; k < nblocks; k++) {
                float2 w = *(const float2*)&W[off + (size_t)k * stride];
                float2 b = *(const float2*)&Bb[off + (size_t)k * stride];
                float2 o = make_float2(1.f - w.x, 1.f - w.y);
                p.x *= o.x; p.y *= o.y;
                c.x = c.x * o.x + b.x; c.y = c.y * o.y + b.y;
            }
        }
        const float ri = rw[gi];
        pt[row * 33 + cl] = ri * p.x; pt[row * 33 + cl + 1] = ri * p.y;
        cp[row * 33 + cl] = ri * c.x; cp[row * 33 + cl + 1] = ri * c.y;
        __syncthreads();

        if (tid < 32) {
            float s = 0.f;
#pragma unroll
            for (int i = 0; i < 16; i++) s += cp[i * 33 + tid];
            g_cbarp[bi2][bj * 32 + tid] = s;
        }
        // Pt pack: this half owns slots [bih*8, bih*8+8) of each row j.
        // s_loc in [0,8): local i0 = (s_loc>>2)*8 + (s_loc&3); pairs (i0, i0+4).
        {
            const int j = tid >> 3, s_loc = tid & 7;
            const int i0 = ((s_loc >> 2) << 3) + (s_loc & 3);
            const int dst = ((bj * 4 + bi / 3) * 32 + j) * PSB
                          + (bi % 3) * 16 + bih * 8 + s_loc;
            g_Ptp[dst] = make_uint2(f2tf32(pt[i0 * 33 + j]),
                                    f2tf32(pt[(i0 + 4) * 33 + j]));
        }
    } else if (bid < 352) {
        // ---- v1 pack: (rb, bih): stage 16 rows, emit p in [bih*8, bih*8+8) ----
        const int u = bid - 288;
        const int rb = u >> 1, bih = u & 1;
        float4* stg = (float4*)smc;
        float* stf = (float*)smc;
#pragma unroll
        for (int j = 0; j < 6; j++) {
            int t = tid + j * 256;             // 0..1535 (16 rows x 96 f4)
            int r = t / 96, c4 = t - r * 96;
            stg[r * FP4PITCH + c4] =
                *(const float4*)&v1[(size_t)(rb * 32 + bih * 16 + r) * DIMN + c4 * 4];
        }
        __syncthreads();
#pragma unroll
        for (int j = 0; j < 6; j++) {
            int e = tid + j * 256;             // 0..1535
            int ks = e >> 5, pl = (e >> 2) & 7, t4 = e & 3;
            int p = bih * 8 + pl;
            int rem = ks * 64 + p * 4 + t4;
            int k0 = ks * 8 + t4;
            const float* r0 = stf + pl * (FP4PITCH * 4);       // local rows pl, pl+8
            const float* r1 = r0 + 8 * (FP4PITCH * 4);
            g_v1p4[rb * A4_CNT + rem] =
                make_uint4(f2tf32(r0[k0]), f2tf32(r0[k0 + 4]),
                           f2tf32(r1[k0]), f2tf32(r1[k0 + 4]));
        }
    } else {
        // ---- linW pack: (nb, bih): stage 16 rows, emit padded chunk-major ----
        const int u = bid - 352;
        const int nb = u >> 1, bih = u & 1;
        float4* stg = (float4*)smc;
        float* stf = (float*)smc;
#pragma unroll
        for (int j = 0; j < 6; j++) {
            int t = tid + j * 256;
            int r = t / 96, c4 = t - r * 96;
            stg[r * FP4PITCH + c4] =
                *(const float4*)&linW[(size_t)(nb * 32 + bih * 16 + r) * DIMN + c4 * 4];
        }
        __syncthreads();
#pragma unroll
        for (int j = 0; j < 12; j++) {
            int q = tid + j * 256;             // 0..3071 (16 rows x NP slots)
            int rl = q / NP, s = q - rl * NP;
            int row = bih * 16 + rl;
            int k0 = ((s >> 2) << 3) + (s & 3);
            int chunk = s / 48, sloc = s - chunk * 48;
            const float* r0 = stf + rl * (FP4PITCH * 4);
            g_lwp[((nb * 4 + chunk) * 32 + row) * PSB + sloc] =
                make_uint2(f2tf32(r0[k0]), f2tf32(r0[k0 + 4]));
        }
    }
}

// ---------------------------------------------------------------------------
// tf32 mma.sync GEMM (proven body). 32x32 tile, 8 warps = wn(2) x kh(4),
// K = 4 chunks of 96, 2-stage bulk-copy ring, cross-quarter smem reduction.
// MODE 0: t = v2 .* (v1 @ rwP) - sum(cbarp)  -> g_tp4 (packed)
// MODE 1: out = (t @ linW^T) + linb          -> f32 Out
// ---------------------------------------------------------------------------
template <int MODE>
__global__ __launch_bounds__(256, 4)
void mma_gemm(const uint4* __restrict__ Ap4, const uint2* __restrict__ Bp,
              const float* __restrict__ v2, const float* __restrict__ linb,
              float* __restrict__ Out) {
    extern __shared__ __align__(16) char smc[];
    __shared__ __align__(8) uint64_t mbar_sh[2];

    const int tid = threadIdx.x, lane = tid & 31, wid = tid >> 5;
    const int g = lane >> 2, t4 = lane & 3;
    const int wn = wid & 1, kh = wid >> 1;
    const int rb = blockIdx.y, nx = blockIdx.x;
    const int m0 = rb * 32, n0 = nx * 32;

    const uint32_t sbase = smem_u32(smc);
    const uint32_t mb0 = smem_u32(mbar_sh);
    const char* aSrc = (const char*)(Ap4 + (size_t)rb * A4_CNT);
    const char* bSrc = (const char*)(Bp + (size_t)nx * 4 * BPAD_CHUNK);

    if (tid == 0) { mbar_init(mb0, 1); mbar_init(mb0 + 8, 1); }
    __syncthreads();

    auto issueChunk = [&](int c, int buf) {
        const uint32_t mb = mb0 + buf * 8;
        mbar_expect(mb, STAGE_B);
        bulk_g2s(sbase + buf * STAGE_B, aSrc + c * ABYTES_C, ABYTES_C, mb);
        bulk_g2s(sbase + buf * STAGE_B + ABYTES_C, bSrc + c * BBYTES_C, BBYTES_C, mb);
    };

    if (tid == 0) { issueChunk(0, 0); issueChunk(1, 1); }

    float acc[2][2][4] = {};

#pragma unroll
    for (int c = 0; c < 4; c++) {
        const int buf = c & 1;
        MBAR_WAIT(mb0 + buf * 8, c >> 1);

        const uint4* A4b = (const uint4*)(smc + buf * STAGE_B);
        const uint2* Bsb = (const uint2*)(smc + buf * STAGE_B + ABYTES_C);
        const uint4* aP = &A4b[kh * 3 * 64 + g * 4 + t4];
        const uint2* bP = &Bsb[(wn * 16 + g) * PSB + kh * 12 + t4];
#pragma unroll
        for (int l = 0; l < 3; l++) {
            uint4 qa0 = aP[l * 64], qa1 = aP[l * 64 + 32];
            uint2 qb0 = bP[l * 4],  qb1 = bP[8 * PSB + l * 4];
            uint32_t a0[4] = {qa0.x, qa0.z, qa0.y, qa0.w};
            uint32_t a1[4] = {qa1.x, qa1.z, qa1.y, qa1.w};
            mma8(acc[0][0], a0, qb0.x, qb0.y);
            mma8(acc[0][1], a0, qb1.x, qb1.y);
            mma8(acc[1][0], a1, qb0.x, qb0.y);
            mma8(acc[1][1], a1, qb1.x, qb1.y);
        }
        __syncthreads();
        if (c < 2 && tid == 0) issueChunk(c + 2, buf);
    }

    // cross-quarter reduction via smem (reuse ring region)
    float* red = (float*)smc;
    if (kh > 0) {
        float* r = red + (kh - 1) * (32 * 34);
#pragma unroll
        for (int mi = 0; mi < 2; mi++) {
            const int rl = mi * 16 + g;
#pragma unroll
            for (int nf = 0; nf < 2; nf++) {
                const int cc = wn * 16 + nf * 8 + 2 * t4;
                *(float2*)&r[rl * 34 + cc]       = make_float2(acc[mi][nf][0], acc[mi][nf][1]);
                *(float2*)&r[(rl + 8) * 34 + cc] = make_float2(acc[mi][nf][2], acc[mi][nf][3]);
            }
        }
    }
    __syncthreads();
    if (kh > 0) return;

#pragma unroll
    for (int b = 0; b < 3; b++) {
        const float* r = red + b * (32 * 34);
#pragma unroll
        for (int mi = 0; mi < 2; mi++) {
            const int rl = mi * 16 + g;
#pragma unroll
            for (int nf = 0; nf < 2; nf++) {
                const int cc = wn * 16 + nf * 8 + 2 * t4;
                float2 p0 = *(const float2*)&r[rl * 34 + cc];
                float2 p1 = *(const float2*)&r[(rl + 8) * 34 + cc];
                acc[mi][nf][0] += p0.x; acc[mi][nf][1] += p0.y;
                acc[mi][nf][2] += p1.x; acc[mi][nf][3] += p1.y;
            }
        }
    }

#pragma unroll
    for (int mi = 0; mi < 2; mi++) {
        const int r0 = m0 + mi * 16 + g, r1 = r0 + 8;
#pragma unroll
        for (int nf = 0; nf < 2; nf++) {
            const int C = n0 + wn * 16 + nf * 8 + 2 * t4;
            if (MODE == 0) {
                float2 cb = make_float2(0.f, 0.f);
#pragma unroll
                for (int b = 0; b < 24; b++) {
                    float2 p = *(const float2*)&g_cbarp[b][C];
                    cb.x += p.x; cb.y += p.y;
                }
                float2 va = *(const float2*)&v2[r0 * DIMN + C];
                float2 vb = *(const float2*)&v2[r1 * DIMN + C];
                float c0 = va.x * acc[mi][nf][0] - cb.x;
                float c1 = va.y * acc[mi][nf][1] - cb.y;
                float c2 = vb.x * acc[mi][nf][2] - cb.x;
                float c3 = vb.y * acc[mi][nf][3] - cb.y;
                float u0 = __shfl_down_sync(0xffffffffu, c0, 2);
                float u1 = __shfl_down_sync(0xffffffffu, c1, 2);
                float u2 = __shfl_down_sync(0xffffffffu, c2, 2);
                float u3 = __shfl_down_sync(0xffffffffu, c3, 2);
                if (t4 < 2) {
                    const int p = mi * 8 + g;
                    const int ks_g = (n0 + wn * 16 + nf * 8) >> 3;
                    size_t base = (size_t)rb * A4_CNT + ks_g * 64 + p * 4;
                    g_tp4[base + 2 * t4] =
                        make_uint4(f2tf32(c0), f2tf32(u0), f2tf32(c2), f2tf32(u2));
                    g_tp4[base + 2 * t4 + 1] =
                        make_uint4(f2tf32(c1), f2tf32(u1), f2tf32(c3), f2tf32(u3));
                }
            } else {
                float2 lb = *(const float2*)&linb[C];
                *(float2*)&Out[r0 * DIMN + C] =
                    make_float2(acc[mi][nf][0] + lb.x, acc[mi][nf][1] + lb.y);
                *(float2*)&Out[r1 * DIMN + C] =
                    make_float2(acc[mi][nf][2] + lb.x, acc[mi][nf][3] + lb.y);
            }
        }
    }
}

// ---------------------------------------------------------------------------
// Launch. Inputs: v1, v2, block_W, block_b, row_weights, lin_W, lin_b
// ---------------------------------------------------------------------------
extern "C" void kernel_launch(void* const* d_in, const int* in_sizes, int n_in,
                              void* d_out, int out_size) {
    const float* v1   = (const float*)d_in[0];
    const float* v2   = (const float*)d_in[1];
    const float* bW   = (const float*)d_in[2];
    const float* bB   = (const float*)d_in[3];
    const float* rw   = (const float*)d_in[4];
    const float* linW = (const float*)d_in[5];
    const float* linb = (const float*)d_in[6];

    const int nblocks = in_sizes[2] / (DIMN * DIMN);

    uint4 *gv1p4, *gtp4; uint2 *glwp, *gPtp;
    cudaGetSymbolAddress((void**)&gv1p4, g_v1p4);
    cudaGetSymbolAddress((void**)&gtp4,  g_tp4);
    cudaGetSymbolAddress((void**)&glwp,  g_lwp);
    cudaGetSymbolAddress((void**)&gPtp,  g_Ptp);

    cudaFuncSetAttribute(pack_prep_kernel,
                         cudaFuncAttributeMaxDynamicSharedMemorySize, SMEM_PACK);
    cudaFuncSetAttribute(mma_gemm<0>,
                         cudaFuncAttributeMaxDynamicSharedMemorySize, SMEM_GEMM);
    cudaFuncSetAttribute(mma_gemm<1>,
                         cudaFuncAttributeMaxDynamicSharedMemorySize, SMEM_GEMM);

    pack_prep_kernel<<<376, 256, SMEM_PACK>>>(v1, linW, bW, bB, rw, nblocks);
    dim3 grid(12, 32);
    mma_gemm<0><<<grid, 256, SMEM_GEMM>>>(gv1p4, gPtp, v2, nullptr, nullptr);
    mma_gemm<1><<<grid, 256, SMEM_GEMM>>>(gtp4, glwp, nullptr, linb, (float*)d_out);
}